// round 3
// baseline (speedup 1.0000x reference)
#include <cuda_runtime.h>
#include <math.h>

// ---------------------------------------------------------------------------
// FormationOptimizer: fully-connected GNN, N=512, 3 message-passing rounds.
// Edge layer0 factorized: A[i] + B[j] + dist*wd. Persistent edge kernel,
// packed fma.rn.f32x2, duplicated H1 layout for MOV-free stage 3.
// ---------------------------------------------------------------------------

#define NN 512
#define FD 64
#define H0D 128
#define H1D 64
#define H2D 32

typedef unsigned long long ull;

__device__ float g_NF[NN * FD];
__device__ float g_DIST[NN * NN];
__device__ float g_A[NN * H0D];
__device__ float g_B[NN * H0D];
__device__ float g_AGG[NN * H2D];

__device__ __forceinline__ ull fma2(ull a, ull b, ull c) {
    ull d;
    asm("fma.rn.f32x2 %0, %1, %2, %3;" : "=l"(d) : "l"(a), "l"(b), "l"(c));
    return d;
}
__device__ __forceinline__ ull pack2(float x) {
    ull r;
    asm("mov.b64 %0, {%1, %1};" : "=l"(r) : "f"(x));
    return r;
}
__device__ __forceinline__ float2 unpack2(ull v) {
    float2 f;
    asm("mov.b64 {%0, %1}, %2;" : "=f"(f.x), "=f"(f.y) : "l"(v));
    return f;
}

// ---------------------------------------------------------------------------
__global__ void k_init(const float* __restrict__ states, const float* __restrict__ obj) {
    int i = blockIdx.x, t = threadIdx.x;
    if (t < FD) g_NF[i * FD + t] = (t < 6) ? states[i * 6 + t] : obj[t - 6];
    float px = states[i * 6 + 0], py = states[i * 6 + 1], pz = states[i * 6 + 2];
    for (int j = t; j < NN; j += blockDim.x) {
        float dx = states[j * 6 + 0] - px;
        float dy = states[j * 6 + 1] - py;
        float dz = states[j * 6 + 2] - pz;
        g_DIST[i * NN + j] = sqrtf(dx * dx + dy * dy + dz * dz);
    }
}

// ---------------------------------------------------------------------------
// k_proj: A = nf@ew0[0:64], B = nf@ew0[64:128]+eb0. Only needed for iter 0
// (k_node produces A/B for later iterations). Also zeroes g_AGG.
// ---------------------------------------------------------------------------
#define PROJ_SMEM (16384 + 512)
__global__ void __launch_bounds__(256) k_proj(const float* __restrict__ ew0,
                                              const float* __restrict__ eb0) {
    extern __shared__ float sm[];
    float* sE = sm;
    float* snf = sm + 16384;
    const int t = threadIdx.x;
    const int nb8 = blockIdx.x * 8;

    for (int q = 0; q < 16; q++)
        *(float4*)(sE + q * 1024 + t * 4) = *(const float4*)(ew0 + q * 1024 + t * 4);
    for (int q = 0; q < 2; q++) {
        int idx = q * 256 + t;
        snf[idx] = g_NF[nb8 * 64 + idx];
    }
    g_AGG[blockIdx.x * 256 + t] = 0.f;
    __syncthreads();

    const int nd = t >> 5;
    const int k4 = (t & 31) * 4;
    float4 a = make_float4(0.f, 0.f, 0.f, 0.f);
    float4 b = make_float4(0.f, 0.f, 0.f, 0.f);
#pragma unroll 4
    for (int c = 0; c < 64; c++) {
        float v = snf[nd * 64 + c];
        float4 wa = *(const float4*)(sE + c * 128 + k4);
        float4 wb = *(const float4*)(sE + (64 + c) * 128 + k4);
        a.x = fmaf(v, wa.x, a.x); a.y = fmaf(v, wa.y, a.y);
        a.z = fmaf(v, wa.z, a.z); a.w = fmaf(v, wa.w, a.w);
        b.x = fmaf(v, wb.x, b.x); b.y = fmaf(v, wb.y, b.y);
        b.z = fmaf(v, wb.z, b.z); b.w = fmaf(v, wb.w, b.w);
    }
    float4 e = *(const float4*)(eb0 + k4);
    b.x += e.x; b.y += e.y; b.z += e.z; b.w += e.w;
    *(float4*)(g_A + (nb8 + nd) * 128 + k4) = a;
    *(float4*)(g_B + (nb8 + nd) * 128 + k4) = b;
}

// ---------------------------------------------------------------------------
// k_edge: persistent, grid = 296 (2 CTAs/SM), 256 threads.
// Work items = 4096 tiles: item = j*8 + tile, tile = 64 senders.
// ---------------------------------------------------------------------------
#define OFF_W1 0          // 128*64           = 8192
#define OFF_W2 8192       // 64*32            = 2048
#define OFF_H0 10240      // 128 k x 66       = 8448
#define OFF_H1 18688      // 64 n x 132 (dup) = 8448
#define OFF_B1 27136      // 64
#define OFF_B2 27200      // 32
#define EDGE_SMEM 27232   // floats = 108928 bytes

#define EDGE_GRID 296

__global__ void __launch_bounds__(256, 2) k_edge(
    const float* __restrict__ ew0, const float* __restrict__ ew1,
    const float* __restrict__ eb1, const float* __restrict__ ew2,
    const float* __restrict__ eb2)
{
    extern __shared__ float sm[];
    float* sW1  = sm + OFF_W1;
    float* sW2  = sm + OFF_W2;
    float* sH0  = sm + OFF_H0;
    float* sH1d = sm + OFF_H1;
    float* sB1  = sm + OFF_B1;
    float* sB2  = sm + OFF_B2;

    const int t = threadIdx.x;
    const int lane = t & 31;
    const int wrp  = t >> 5;

    // stage weights once per CTA
#pragma unroll
    for (int q = 0; q < 8; q++)
        *(float4*)(sW1 + q * 1024 + t * 4) = *(const float4*)(ew1 + q * 1024 + t * 4);
#pragma unroll
    for (int q = 0; q < 2; q++)
        *(float4*)(sW2 + q * 1024 + t * 4) = *(const float4*)(ew2 + q * 1024 + t * 4);
    if (t < 64) sB1[t] = eb1[t];
    if (t < 32) sB2[t] = eb2[t];

    const int k1 = t & 127;          // stage1 hidden index
    const int eh = (t >> 7) * 32;    // stage1 edge sub-range
    const float wdk = ew0[128 * H0D + k1];   // dist weight (constant)

    const int e0 = lane * 2;         // stage2/3: 2 edges per thread
    const int nb = wrp * 8;          // stage2: 8 n per warp
    const int mb = wrp * 4;          // stage3: 4 m per warp

    __syncthreads();

    for (int item = blockIdx.x; item < NN * 8; item += gridDim.x) {
        const int j = item >> 3;
        const int ibase = (item & 7) * 64;

        // ---- stage 1: H0[k][e] = relu(A[i][k] + B[j][k] + d*wd[k]) ----
        {
            const float bk = g_B[j * H0D + k1];
            const float* Ap = g_A + (ibase + eh) * H0D + k1;
            const float* Dp = g_DIST + j * NN + ibase + eh;
            float* hp = sH0 + k1 * 66 + eh;
#pragma unroll 8
            for (int e = 0; e < 32; e++) {
                float h = fmaf(Dp[e], wdk, Ap[e * H0D] + bk);
                hp[e] = fmaxf(h, 0.f);
            }
        }
        __syncthreads();   // sync_A: H0 ready; also fences prev item's H1d readers

        // ---- stage 2: H1 = relu(H0 @ W1 + b1), written duplicated ----
        {
            ull acc[2][4];
            {
                ulonglong2 b0 = *(const ulonglong2*)(sB1 + nb);
                ulonglong2 b1 = *(const ulonglong2*)(sB1 + nb + 4);
                acc[0][0] = b0.x; acc[0][1] = b0.y; acc[0][2] = b1.x; acc[0][3] = b1.y;
                acc[1][0] = b0.x; acc[1][1] = b0.y; acc[1][2] = b1.x; acc[1][3] = b1.y;
            }
#pragma unroll 4
            for (int k = 0; k < 128; k++) {
                float2 h = *(const float2*)(sH0 + k * 66 + e0);
                ull hx = pack2(h.x);
                ull hy = pack2(h.y);
                ulonglong2 w0 = *(const ulonglong2*)(sW1 + k * 64 + nb);
                ulonglong2 w1 = *(const ulonglong2*)(sW1 + k * 64 + nb + 4);
                acc[0][0] = fma2(hx, w0.x, acc[0][0]);
                acc[0][1] = fma2(hx, w0.y, acc[0][1]);
                acc[0][2] = fma2(hx, w1.x, acc[0][2]);
                acc[0][3] = fma2(hx, w1.y, acc[0][3]);
                acc[1][0] = fma2(hy, w0.x, acc[1][0]);
                acc[1][1] = fma2(hy, w0.y, acc[1][1]);
                acc[1][2] = fma2(hy, w1.x, acc[1][2]);
                acc[1][3] = fma2(hy, w1.y, acc[1][3]);
            }
#pragma unroll
            for (int p = 0; p < 4; p++) {
                int n0 = nb + 2 * p;
                float2 u0 = unpack2(acc[0][p]);   // edge e0:   (n0, n0+1)
                float2 u1 = unpack2(acc[1][p]);   // edge e0+1: (n0, n0+1)
                float h00 = fmaxf(u0.x, 0.f);
                float h01 = fmaxf(u0.y, 0.f);
                float h10 = fmaxf(u1.x, 0.f);
                float h11 = fmaxf(u1.y, 0.f);
                *(float2*)(sH1d + n0 * 132 + 2 * e0)           = make_float2(h00, h00);
                *(float2*)(sH1d + n0 * 132 + 2 * e0 + 2)       = make_float2(h10, h10);
                *(float2*)(sH1d + (n0 + 1) * 132 + 2 * e0)     = make_float2(h01, h01);
                *(float2*)(sH1d + (n0 + 1) * 132 + 2 * e0 + 2) = make_float2(h11, h11);
            }
        }
        __syncthreads();   // sync_B: H1d ready; also guards H0 overwrite next item

        // ---- stage 3: H2 = relu(H1 @ W2 + b2), masked sum-aggregate ----
        {
            ull acc[2][2];
            {
                ulonglong2 bb = *(const ulonglong2*)(sB2 + mb);
                acc[0][0] = bb.x; acc[0][1] = bb.y;
                acc[1][0] = bb.x; acc[1][1] = bb.y;
            }
#pragma unroll 4
            for (int n = 0; n < 64; n++) {
                ulonglong2 h = *(const ulonglong2*)(sH1d + n * 132 + 2 * e0);
                ulonglong2 w = *(const ulonglong2*)(sW2 + n * 32 + mb);
                acc[0][0] = fma2(h.x, w.x, acc[0][0]);
                acc[0][1] = fma2(h.x, w.y, acc[0][1]);
                acc[1][0] = fma2(h.y, w.x, acc[1][0]);
                acc[1][1] = fma2(h.y, w.y, acc[1][1]);
            }
            const bool me0 = (ibase + e0) != j;
            const bool me1 = (ibase + e0 + 1) != j;
            float pm[4];
#pragma unroll
            for (int p = 0; p < 2; p++) {
                float2 u0 = unpack2(acc[0][p]);   // edge e0:   (m0, m0+1)
                float2 u1 = unpack2(acc[1][p]);   // edge e0+1: (m0, m0+1)
                float s0 = 0.f, s1 = 0.f;
                if (me0) { s0 += fmaxf(u0.x, 0.f); s1 += fmaxf(u0.y, 0.f); }
                if (me1) { s0 += fmaxf(u1.x, 0.f); s1 += fmaxf(u1.y, 0.f); }
                pm[2 * p] = s0; pm[2 * p + 1] = s1;
            }
#pragma unroll
            for (int off = 16; off > 0; off >>= 1) {
#pragma unroll
                for (int q = 0; q < 4; q++)
                    pm[q] += __shfl_xor_sync(0xffffffffu, pm[q], off);
            }
            if (lane == 0) {
#pragma unroll
                for (int q = 0; q < 4; q++)
                    atomicAdd(&g_AGG[j * H2D + mb + q], pm[q]);
            }
        }
        // no sync here: next stage1 writes H0 only; H1d readers fenced by sync_A
    }
}

// ---------------------------------------------------------------------------
// k_node: 64 CTAs x 8 nodes. Node MLP + residual, then fused projection
// (A/B for the next edge pass) and g_AGG zeroing.
// ---------------------------------------------------------------------------
#define NOD_W0 0        // 96*128  = 12288
#define NOD_W1 12288    // 128*64  = 8192
#define NOD_W2 20480    // 64*32   = 2048
#define NOD_WO 22528    // 32*64   = 2048
#define NOD_Y  24576    // 8*96    = 768
#define NOD_H0 25344    // 8*128   = 1024
#define NOD_H1 26368    // 8*64    = 512
#define NOD_H2 26880    // 8*32    = 256
#define NOD_EW 27136    // 128*128 = 16384 (ew0 rows 0..127)
#define NOD_NF 43520    // 8*64    = 512 (new node features)
#define NODE_SMEM 44032 // floats = 176128 bytes

__global__ void __launch_bounds__(256) k_node(
    const float* __restrict__ nw0, const float* __restrict__ nb0,
    const float* __restrict__ nw1, const float* __restrict__ nb1,
    const float* __restrict__ nw2, const float* __restrict__ nb2,
    const float* __restrict__ nwo, const float* __restrict__ nbo,
    const float* __restrict__ ew0, const float* __restrict__ eb0)
{
    extern __shared__ float sm[];
    float* sw0 = sm + NOD_W0;
    float* sw1 = sm + NOD_W1;
    float* sw2 = sm + NOD_W2;
    float* swo = sm + NOD_WO;
    float* sy  = sm + NOD_Y;
    float* sh0 = sm + NOD_H0;
    float* sh1 = sm + NOD_H1;
    float* sh2 = sm + NOD_H2;
    float* sEW = sm + NOD_EW;
    float* sNF = sm + NOD_NF;

    const int t = threadIdx.x;
    const int nb8 = blockIdx.x * 8;

#pragma unroll
    for (int q = 0; q < 12; q++)
        *(float4*)(sw0 + q * 1024 + t * 4) = *(const float4*)(nw0 + q * 1024 + t * 4);
#pragma unroll
    for (int q = 0; q < 8; q++)
        *(float4*)(sw1 + q * 1024 + t * 4) = *(const float4*)(nw1 + q * 1024 + t * 4);
#pragma unroll
    for (int q = 0; q < 2; q++)
        *(float4*)(sw2 + q * 1024 + t * 4) = *(const float4*)(nw2 + q * 1024 + t * 4);
#pragma unroll
    for (int q = 0; q < 2; q++)
        *(float4*)(swo + q * 1024 + t * 4) = *(const float4*)(nwo + q * 1024 + t * 4);
#pragma unroll
    for (int q = 0; q < 16; q++)
        *(float4*)(sEW + q * 1024 + t * 4) = *(const float4*)(ew0 + q * 1024 + t * 4);
    // y = [nf | agg]
#pragma unroll
    for (int q = 0; q < 3; q++) {
        int idx = q * 256 + t;
        int nd = idx / 96, c = idx % 96;
        sy[idx] = (c < 64) ? g_NF[(nb8 + nd) * 64 + c]
                           : g_AGG[(nb8 + nd) * 32 + (c - 64)];
    }
    __syncthreads();

    const int nd = t >> 5;
    const int lane = t & 31;
    // layer 0: 96 -> 128
    {
        const int o4 = lane * 4;
        float4 acc = *(const float4*)(nb0 + o4);
#pragma unroll 4
        for (int c = 0; c < 96; c++) {
            float v = sy[nd * 96 + c];
            float4 w = *(const float4*)(sw0 + c * 128 + o4);
            acc.x = fmaf(v, w.x, acc.x); acc.y = fmaf(v, w.y, acc.y);
            acc.z = fmaf(v, w.z, acc.z); acc.w = fmaf(v, w.w, acc.w);
        }
        acc.x = fmaxf(acc.x, 0.f); acc.y = fmaxf(acc.y, 0.f);
        acc.z = fmaxf(acc.z, 0.f); acc.w = fmaxf(acc.w, 0.f);
        *(float4*)(sh0 + nd * 128 + o4) = acc;
    }
    __syncthreads();
    // layer 1: 128 -> 64
    {
        const int o2 = lane * 2;
        float2 acc = *(const float2*)(nb1 + o2);
#pragma unroll 4
        for (int c = 0; c < 128; c++) {
            float v = sh0[nd * 128 + c];
            float2 w = *(const float2*)(sw1 + c * 64 + o2);
            acc.x = fmaf(v, w.x, acc.x); acc.y = fmaf(v, w.y, acc.y);
        }
        acc.x = fmaxf(acc.x, 0.f); acc.y = fmaxf(acc.y, 0.f);
        *(float2*)(sh1 + nd * 64 + o2) = acc;
    }
    __syncthreads();
    // layer 2: 64 -> 32
    {
        float acc = nb2[lane];
#pragma unroll 4
        for (int c = 0; c < 64; c++)
            acc = fmaf(sh1[nd * 64 + c], sw2[c * 32 + lane], acc);
        sh2[nd * 32 + lane] = fmaxf(acc, 0.f);
    }
    __syncthreads();
    // output: 32 -> 64, residual -> g_NF and sNF
    {
        const int o2 = lane * 2;
        float2 acc = *(const float2*)(nbo + o2);
#pragma unroll 4
        for (int c = 0; c < 32; c++) {
            float v = sh2[nd * 32 + c];
            float2 w = *(const float2*)(swo + c * 64 + o2);
            acc.x = fmaf(v, w.x, acc.x); acc.y = fmaf(v, w.y, acc.y);
        }
        float2 y;
        y.x = sy[nd * 96 + o2] + acc.x;
        y.y = sy[nd * 96 + o2 + 1] + acc.y;
        *(float2*)(g_NF + (nb8 + nd) * 64 + o2) = y;
        *(float2*)(sNF + nd * 64 + o2) = y;
    }
    // zero g_AGG for the next edge pass
    g_AGG[blockIdx.x * 256 + t] = 0.f;
    __syncthreads();
    // fused projection: A = nf@ew0[0:64], B = nf@ew0[64:128]+eb0
    {
        const int k4 = lane * 4;
        float4 a = make_float4(0.f, 0.f, 0.f, 0.f);
        float4 b = make_float4(0.f, 0.f, 0.f, 0.f);
#pragma unroll 4
        for (int c = 0; c < 64; c++) {
            float v = sNF[nd * 64 + c];
            float4 wa = *(const float4*)(sEW + c * 128 + k4);
            float4 wb = *(const float4*)(sEW + (64 + c) * 128 + k4);
            a.x = fmaf(v, wa.x, a.x); a.y = fmaf(v, wa.y, a.y);
            a.z = fmaf(v, wa.z, a.z); a.w = fmaf(v, wa.w, a.w);
            b.x = fmaf(v, wb.x, b.x); b.y = fmaf(v, wb.y, b.y);
            b.z = fmaf(v, wb.z, b.z); b.w = fmaf(v, wb.w, b.w);
        }
        float4 e = *(const float4*)(eb0 + k4);
        b.x += e.x; b.y += e.y; b.z += e.z; b.w += e.w;
        *(float4*)(g_A + (nb8 + nd) * 128 + k4) = a;
        *(float4*)(g_B + (nb8 + nd) * 128 + k4) = b;
    }
}

// ---------------------------------------------------------------------------
__global__ void k_read(const float* __restrict__ rw, const float* __restrict__ rb,
                       float* __restrict__ out)
{
    int jn = blockIdx.x * blockDim.x + threadIdx.x;
    if (jn >= NN) return;
    float a0 = rb[0], a1 = rb[1], a2 = rb[2];
#pragma unroll
    for (int c = 0; c < 64; c++) {
        float v = g_NF[jn * FD + c];
        a0 = fmaf(v, rw[c * 3 + 0], a0);
        a1 = fmaf(v, rw[c * 3 + 1], a1);
        a2 = fmaf(v, rw[c * 3 + 2], a2);
    }
    out[jn * 3 + 0] = a0;
    out[jn * 3 + 1] = a1;
    out[jn * 3 + 2] = a2;
}

// ---------------------------------------------------------------------------
extern "C" void kernel_launch(void* const* d_in, const int* in_sizes, int n_in,
                              void* d_out, int out_size)
{
    const float* states = (const float*)d_in[0];
    const float* obj    = (const float*)d_in[1];
    const float* ew0 = (const float*)d_in[2];
    const float* eb0 = (const float*)d_in[3];
    const float* ew1 = (const float*)d_in[4];
    const float* eb1 = (const float*)d_in[5];
    const float* ew2 = (const float*)d_in[6];
    const float* eb2 = (const float*)d_in[7];
    const float* nw0 = (const float*)d_in[8];
    const float* nb0 = (const float*)d_in[9];
    const float* nw1 = (const float*)d_in[10];
    const float* nb1 = (const float*)d_in[11];
    const float* nw2 = (const float*)d_in[12];
    const float* nb2 = (const float*)d_in[13];
    const float* nwo = (const float*)d_in[14];
    const float* nbo = (const float*)d_in[15];
    const float* rw  = (const float*)d_in[16];
    const float* rb  = (const float*)d_in[17];
    float* out = (float*)d_out;

    cudaFuncSetAttribute(k_edge, cudaFuncAttributeMaxDynamicSharedMemorySize,
                         EDGE_SMEM * (int)sizeof(float));
    cudaFuncSetAttribute(k_proj, cudaFuncAttributeMaxDynamicSharedMemorySize,
                         PROJ_SMEM * (int)sizeof(float));
    cudaFuncSetAttribute(k_node, cudaFuncAttributeMaxDynamicSharedMemorySize,
                         NODE_SMEM * (int)sizeof(float));

    k_init<<<NN, 256>>>(states, obj);
    k_proj<<<64, 256, PROJ_SMEM * (int)sizeof(float)>>>(ew0, eb0);
    for (int it = 0; it < 3; it++) {
        k_edge<<<EDGE_GRID, 256, EDGE_SMEM * (int)sizeof(float)>>>(ew0, ew1, eb1, ew2, eb2);
        k_node<<<64, 256, NODE_SMEM * (int)sizeof(float)>>>(nw0, nb0, nw1, nb1,
                                                            nw2, nb2, nwo, nbo,
                                                            ew0, eb0);
    }
    k_read<<<4, 128>>>(rw, rb, out);
}